// round 2
// baseline (speedup 1.0000x reference)
#include <cuda_runtime.h>
#include <math.h>

// GATv2 (L=3, H=4, C=16, D=64) for N=100000 nodes, E=1280000 edges (+N self loops).
// Strategy:
//  - per layer: GEMM -> xl,xr tables (25.6MB each, L2-resident)
//  - single fused edge pass: unnormalized softmax (skip segment_max; alpha identical),
//    vector float4 atomics into num[N,64] + scalar atomics into denom[N,4]
//  - node pass: num/denom + bias + residual + LayerNorm + exact GeLU
//  - edge_index is int32 (JAX x64 disabled): layout [src(E), dst(E)]

#define NNODES 100000
#define DD 64

__device__ __align__(16) float g_xl[NNODES * DD];
__device__ __align__(16) float g_xr[NNODES * DD];
__device__ __align__(16) float g_num[NNODES * DD];
__device__ __align__(16) float g_den[NNODES * 4];
__device__ __align__(16) float g_b0[NNODES * DD];
__device__ __align__(16) float g_b1[NNODES * DD];

// ---------------------------------------------------------------------------
// Zero num + den (per layer, before edge pass)
// ---------------------------------------------------------------------------
__global__ void k_zero(int n) {
    int i = blockIdx.x * blockDim.x + threadIdx.x;
    float4 z = make_float4(0.f, 0.f, 0.f, 0.f);
    int n16 = n * 16;  // num as float4 count
    if (i < n16) {
        ((float4*)g_num)[i] = z;
    } else if (i < n16 + n) {
        ((float4*)g_den)[i - n16] = z;
    }
}

// ---------------------------------------------------------------------------
// GEMM: xl = x @ Wl, xr = x @ Wr   (K = 64, both 64x64 weights in smem)
// Block = 256 threads = 64 nodes x 4 column-groups of 16.
// ---------------------------------------------------------------------------
__global__ __launch_bounds__(256) void k_gemm(const float* __restrict__ x,
                                              const float* __restrict__ Wl,
                                              const float* __restrict__ Wr,
                                              int n) {
    __shared__ float sWl[64][64];
    __shared__ float sWr[64][64];
    __shared__ float sxT[64][64];  // transposed tile: [k][node]

    int nodeBase = blockIdx.x * 64;

    for (int i = threadIdx.x; i < 64 * 64; i += 256) {
        sWl[i >> 6][i & 63] = Wl[i];
        sWr[i >> 6][i & 63] = Wr[i];
        int r = i >> 6, c = i & 63;
        int node = nodeBase + r;
        float v = (node < n) ? x[(size_t)node * DD + c] : 0.f;
        sxT[c][r] = v;
    }
    __syncthreads();

    int local = threadIdx.x >> 2;          // node in tile (0..63)
    int cg = (threadIdx.x & 3) << 4;       // output column base (0,16,32,48)

    float accL[16], accR[16];
#pragma unroll
    for (int c = 0; c < 16; c++) { accL[c] = 0.f; accR[c] = 0.f; }

#pragma unroll 4
    for (int k = 0; k < 64; k++) {
        float xv = sxT[k][local];
        const float4* wl = (const float4*)&sWl[k][cg];
        const float4* wr = (const float4*)&sWr[k][cg];
#pragma unroll
        for (int q = 0; q < 4; q++) {
            float4 a = wl[q];
            float4 b = wr[q];
            accL[q * 4 + 0] = fmaf(xv, a.x, accL[q * 4 + 0]);
            accL[q * 4 + 1] = fmaf(xv, a.y, accL[q * 4 + 1]);
            accL[q * 4 + 2] = fmaf(xv, a.z, accL[q * 4 + 2]);
            accL[q * 4 + 3] = fmaf(xv, a.w, accL[q * 4 + 3]);
            accR[q * 4 + 0] = fmaf(xv, b.x, accR[q * 4 + 0]);
            accR[q * 4 + 1] = fmaf(xv, b.y, accR[q * 4 + 1]);
            accR[q * 4 + 2] = fmaf(xv, b.z, accR[q * 4 + 2]);
            accR[q * 4 + 3] = fmaf(xv, b.w, accR[q * 4 + 3]);
        }
    }

    int node = nodeBase + local;
    if (node < n) {
        float4* outl = (float4*)&g_xl[(size_t)node * DD + cg];
        float4* outr = (float4*)&g_xr[(size_t)node * DD + cg];
#pragma unroll
        for (int q = 0; q < 4; q++) {
            outl[q] = make_float4(accL[q * 4 + 0], accL[q * 4 + 1], accL[q * 4 + 2], accL[q * 4 + 3]);
            outr[q] = make_float4(accR[q * 4 + 0], accR[q * 4 + 1], accR[q * 4 + 2], accR[q * 4 + 3]);
        }
    }
}

// ---------------------------------------------------------------------------
// Edge pass: 16 threads/edge. Each thread handles one float4 (4 channels of one
// head). Butterfly-reduce the per-head logit over 4 lanes, exp, then vector-RED
// p*xl into num[dst] and scalar-RED p into denom[dst][h].
// Softmax max-shift skipped (cancels exactly in alpha; logits are O(1)).
// ---------------------------------------------------------------------------
__global__ __launch_bounds__(256) void k_edge(const int* __restrict__ ei,
                                              const float* __restrict__ att,
                                              int Etot, int E) {
    int t = blockIdx.x * blockDim.x + threadIdx.x;
    int e = t >> 4;
    if (e >= Etot) return;
    int lane = t & 15;

    int s, d;
    if (e < E) {
        s = ei[e];            // broadcast load across 16 lanes
        d = ei[E + e];
    } else {
        s = e - E;            // self loop
        d = s;
    }

    int j = lane << 2;  // channel offset 0..60 ; head = lane>>2
    float4 a = *(const float4*)&g_xl[(size_t)s * DD + j];
    float4 b = *(const float4*)&g_xr[(size_t)d * DD + j];
    float4 av = __ldg((const float4*)(att + j));

    float m0 = a.x + b.x, m1 = a.y + b.y, m2 = a.z + b.z, m3 = a.w + b.w;
    m0 = (m0 > 0.f) ? m0 : 0.2f * m0;
    m1 = (m1 > 0.f) ? m1 : 0.2f * m1;
    m2 = (m2 > 0.f) ? m2 : 0.2f * m2;
    m3 = (m3 > 0.f) ? m3 : 0.2f * m3;

    float part = m0 * av.x + m1 * av.y + m2 * av.z + m3 * av.w;
    unsigned mask = __activemask();
    part += __shfl_xor_sync(mask, part, 1);
    part += __shfl_xor_sync(mask, part, 2);

    float p = expf(part);

    float4 v = make_float4(p * a.x, p * a.y, p * a.z, p * a.w);
    atomicAdd((float4*)&g_num[(size_t)d * DD + j], v);  // sm_90+ vector atomic
    if ((lane & 3) == 0) {
        atomicAdd(&g_den[(size_t)d * 4 + (lane >> 2)], p);
    }
}

// ---------------------------------------------------------------------------
// Node pass: out = gelu(layernorm(num/den + bias + x_res))
// One warp per node, 2 channels per lane.
// ---------------------------------------------------------------------------
__global__ __launch_bounds__(256) void k_node(const float* __restrict__ xres,
                                              const float* __restrict__ bias,
                                              const float* __restrict__ gamma,
                                              const float* __restrict__ beta,
                                              float* __restrict__ out, int n) {
    int gt = blockIdx.x * blockDim.x + threadIdx.x;
    int node = gt >> 5;
    if (node >= n) return;
    int lane = gt & 31;
    int j = lane * 2;

    float2 nm = *(const float2*)&g_num[(size_t)node * DD + j];
    float den = g_den[(size_t)node * 4 + (lane >> 3)];
    float inv = 1.f / den;
    float2 xr2 = *(const float2*)&xres[(size_t)node * DD + j];
    float2 bi = *(const float2*)&bias[j];

    float v0 = nm.x * inv + bi.x + xr2.x;
    float v1 = nm.y * inv + bi.y + xr2.y;

    float s = v0 + v1;
    float s2 = v0 * v0 + v1 * v1;
#pragma unroll
    for (int o = 16; o; o >>= 1) {
        s += __shfl_xor_sync(0xffffffffu, s, o);
        s2 += __shfl_xor_sync(0xffffffffu, s2, o);
    }
    float mu = s * (1.f / 64.f);
    float var = s2 * (1.f / 64.f) - mu * mu;
    float rstd = rsqrtf(var + 1e-5f);

    float2 ga = *(const float2*)&gamma[j];
    float2 be = *(const float2*)&beta[j];
    float y0 = (v0 - mu) * rstd * ga.x + be.x;
    float y1 = (v1 - mu) * rstd * ga.y + be.y;

    // exact GeLU: 0.5*x*(1+erf(x/sqrt(2)))
    y0 = 0.5f * y0 * (1.f + erff(y0 * 0.70710678118654752f));
    y1 = 0.5f * y1 * (1.f + erff(y1 * 0.70710678118654752f));

    *(float2*)&out[(size_t)node * DD + j] = make_float2(y0, y1);
}

// ---------------------------------------------------------------------------
extern "C" void kernel_launch(void* const* d_in, const int* in_sizes, int n_in,
                              void* d_out, int out_size) {
    const float* x = (const float*)d_in[0];
    const int* ei = (const int*)d_in[1];   // int32: [src(E), dst(E)]
    const float* Wl = (const float*)d_in[2];
    const float* Wr = (const float*)d_in[3];
    const float* att = (const float*)d_in[4];
    const float* bias = (const float*)d_in[5];
    const float* gamma = (const float*)d_in[6];
    const float* beta = (const float*)d_in[7];

    int n = in_sizes[0] / DD;
    int E = in_sizes[1] / 2;
    int Lnum = in_sizes[2] / (DD * DD);

    float *b0p = nullptr, *b1p = nullptr;
    cudaGetSymbolAddress((void**)&b0p, g_b0);
    cudaGetSymbolAddress((void**)&b1p, g_b1);

    const float* cur = x;
    int Etot = E + n;
    long long edgeThreads = (long long)Etot * 16;
    int edgeBlocks = (int)((edgeThreads + 255) / 256);

    for (int i = 0; i < Lnum; i++) {
        k_gemm<<<(n + 63) / 64, 256>>>(cur, Wl + (size_t)i * DD * DD,
                                       Wr + (size_t)i * DD * DD, n);
        k_zero<<<(n * 17 + 255) / 256, 256>>>(n);
        k_edge<<<edgeBlocks, 256>>>(ei, att + (size_t)i * DD, Etot, E);

        float* outp;
        if (i == Lnum - 1) outp = (float*)d_out;
        else outp = (i & 1) ? b1p : b0p;

        k_node<<<((size_t)n * 32 + 255) / 256, 256>>>(cur, bias + (size_t)i * DD,
                                                      gamma + (size_t)i * DD,
                                                      beta + (size_t)i * DD,
                                                      outp, n);
        cur = outp;
    }
}

// round 3
// speedup vs baseline: 1.1217x; 1.1217x over previous
#include <cuda_runtime.h>
#include <math.h>

// GATv2 (L=3, H=4, C=16, D=64), N=100000, E=1280000 (+N self loops).
// R3 design:
//  - per-launch: counting-sort edges by dst -> CSR (hist + scan + scatter)
//  - per layer: GEMM -> xl,xr (L2-resident), then ONE fused warp-per-node kernel:
//    gather xl[src] over in-edges, unnormalized softmax (max-shift cancels),
//    register accumulation (NO atomics), normalize + bias + residual + LN + GeLU.
//  - edge_index int32, layout [src(E), dst(E)]

#define NNODES 100000
#define NEDGES 1280000
#define DD 64
#define SCAN_BLK 512
#define SCAN_ELEM 8
#define SCAN_TILE (SCAN_BLK * SCAN_ELEM)  // 4096

__device__ __align__(16) float g_xl[NNODES * DD];
__device__ __align__(16) float g_xr[NNODES * DD];
__device__ __align__(16) float g_b0[NNODES * DD];
__device__ __align__(16) float g_b1[NNODES * DD];
__device__ int g_cnt[NNODES];
__device__ int g_tmp[NNODES];
__device__ int g_ofs[NNODES];
__device__ int g_rowptr[NNODES + 1];
__device__ int g_bsum[1024];
__device__ int g_ssrc[NEDGES];

// ------------------------- CSR build (once per launch) ----------------------
__global__ void k_cntzero(int n) {
    int i = blockIdx.x * blockDim.x + threadIdx.x;
    if (i < n) g_cnt[i] = 0;
}

__global__ void k_hist(const int* __restrict__ ei, int E) {
    int e = blockIdx.x * blockDim.x + threadIdx.x;
    if (e < E) atomicAdd(&g_cnt[ei[E + e]], 1);
}

__global__ __launch_bounds__(SCAN_BLK) void k_scan1(int n) {
    __shared__ int sh[SCAN_BLK];
    int blk = blockIdx.x;
    int base = blk * SCAN_TILE + threadIdx.x * SCAN_ELEM;
    int t = threadIdx.x;
    int v[SCAN_ELEM];
    int sum = 0;
#pragma unroll
    for (int i = 0; i < SCAN_ELEM; i++) {
        int idx = base + i;
        v[i] = (idx < n) ? g_cnt[idx] : 0;
        sum += v[i];
    }
    sh[t] = sum;
    __syncthreads();
    for (int o = 1; o < SCAN_BLK; o <<= 1) {
        int x = (t >= o) ? sh[t - o] : 0;
        __syncthreads();
        sh[t] += x;
        __syncthreads();
    }
    int run = (t > 0) ? sh[t - 1] : 0;
    if (t == SCAN_BLK - 1) g_bsum[blk] = sh[t];
#pragma unroll
    for (int i = 0; i < SCAN_ELEM; i++) {
        int idx = base + i;
        if (idx < n) g_tmp[idx] = run;
        run += v[i];
    }
}

__global__ __launch_bounds__(1024) void k_scan2(int nb) {
    __shared__ int sh[1024];
    int t = threadIdx.x;
    sh[t] = (t < nb) ? g_bsum[t] : 0;
    __syncthreads();
    for (int o = 1; o < 1024; o <<= 1) {
        int x = (t >= o) ? sh[t - o] : 0;
        __syncthreads();
        sh[t] += x;
        __syncthreads();
    }
    g_bsum[t] = (t > 0) ? sh[t - 1] : 0;
}

__global__ void k_scan3(int n, int E) {
    int i = blockIdx.x * blockDim.x + threadIdx.x;
    if (i < n) {
        int r = g_tmp[i] + g_bsum[i / SCAN_TILE];
        g_rowptr[i] = r;
        g_ofs[i] = r;
    }
    if (i == n) g_rowptr[n] = E;
}

__global__ void k_scatter(const int* __restrict__ ei, int E) {
    int e = blockIdx.x * blockDim.x + threadIdx.x;
    if (e < E) {
        int d = ei[E + e];
        int pos = atomicAdd(&g_ofs[d], 1);
        g_ssrc[pos] = ei[e];
    }
}

// ---------------------------------------------------------------------------
// GEMM: xl = x @ Wl, xr = x @ Wr   (K = 64, both 64x64 weights in smem)
// ---------------------------------------------------------------------------
__global__ __launch_bounds__(256) void k_gemm(const float* __restrict__ x,
                                              const float* __restrict__ Wl,
                                              const float* __restrict__ Wr,
                                              int n) {
    __shared__ float sWl[64][64];
    __shared__ float sWr[64][64];
    __shared__ float sxT[64][64];

    int nodeBase = blockIdx.x * 64;

    for (int i = threadIdx.x; i < 64 * 64; i += 256) {
        sWl[i >> 6][i & 63] = Wl[i];
        sWr[i >> 6][i & 63] = Wr[i];
        int r = i >> 6, c = i & 63;
        int node = nodeBase + r;
        float v = (node < n) ? x[(size_t)node * DD + c] : 0.f;
        sxT[c][r] = v;
    }
    __syncthreads();

    int local = threadIdx.x >> 2;
    int cg = (threadIdx.x & 3) << 4;

    float accL[16], accR[16];
#pragma unroll
    for (int c = 0; c < 16; c++) { accL[c] = 0.f; accR[c] = 0.f; }

#pragma unroll 4
    for (int k = 0; k < 64; k++) {
        float xv = sxT[k][local];
        const float4* wl = (const float4*)&sWl[k][cg];
        const float4* wr = (const float4*)&sWr[k][cg];
#pragma unroll
        for (int q = 0; q < 4; q++) {
            float4 a = wl[q];
            float4 b = wr[q];
            accL[q * 4 + 0] = fmaf(xv, a.x, accL[q * 4 + 0]);
            accL[q * 4 + 1] = fmaf(xv, a.y, accL[q * 4 + 1]);
            accL[q * 4 + 2] = fmaf(xv, a.z, accL[q * 4 + 2]);
            accL[q * 4 + 3] = fmaf(xv, a.w, accL[q * 4 + 3]);
            accR[q * 4 + 0] = fmaf(xv, b.x, accR[q * 4 + 0]);
            accR[q * 4 + 1] = fmaf(xv, b.y, accR[q * 4 + 1]);
            accR[q * 4 + 2] = fmaf(xv, b.z, accR[q * 4 + 2]);
            accR[q * 4 + 3] = fmaf(xv, b.w, accR[q * 4 + 3]);
        }
    }

    int node = nodeBase + local;
    if (node < n) {
        float4* outl = (float4*)&g_xl[(size_t)node * DD + cg];
        float4* outr = (float4*)&g_xr[(size_t)node * DD + cg];
#pragma unroll
        for (int q = 0; q < 4; q++) {
            outl[q] = make_float4(accL[q * 4 + 0], accL[q * 4 + 1], accL[q * 4 + 2], accL[q * 4 + 3]);
            outr[q] = make_float4(accR[q * 4 + 0], accR[q * 4 + 1], accR[q * 4 + 2], accR[q * 4 + 3]);
        }
    }
}

// ---------------------------------------------------------------------------
// Fused aggregation: warp per dst node. Gathers xl[src] over CSR in-edges +
// implicit self loop. Unnormalized softmax (max-shift cancels exactly).
// Register accumulators -> normalize + bias + residual + LayerNorm + GeLU.
// Lane l owns channels {2l, 2l+1}; head = l>>3 (8 lanes per head).
// ---------------------------------------------------------------------------
__global__ __launch_bounds__(256) void k_agg(const float* __restrict__ xres,
                                             const float* __restrict__ att,
                                             const float* __restrict__ bias,
                                             const float* __restrict__ gamma,
                                             const float* __restrict__ beta,
                                             float* __restrict__ out, int n) {
    int d = (blockIdx.x * blockDim.x + threadIdx.x) >> 5;
    if (d >= n) return;
    int lane = threadIdx.x & 31;
    int j = lane * 2;

    float2 xr2 = *(const float2*)&g_xr[(size_t)d * DD + j];
    float2 at2 = *(const float2*)(att + j);

    float accx = 0.f, accy = 0.f, den = 0.f;

    // self loop
    {
        float2 a = *(const float2*)&g_xl[(size_t)d * DD + j];
        float m0 = a.x + xr2.x, m1 = a.y + xr2.y;
        m0 = (m0 > 0.f) ? m0 : 0.2f * m0;
        m1 = (m1 > 0.f) ? m1 : 0.2f * m1;
        float part = m0 * at2.x + m1 * at2.y;
        part += __shfl_xor_sync(0xffffffffu, part, 1);
        part += __shfl_xor_sync(0xffffffffu, part, 2);
        part += __shfl_xor_sync(0xffffffffu, part, 4);
        float p = __expf(part);
        accx = p * a.x;
        accy = p * a.y;
        den = p;
    }

    int begin = g_rowptr[d];
    int end = g_rowptr[d + 1];

    for (int base = begin; base < end; base += 32) {
        int sv = (base + lane < end) ? g_ssrc[base + lane] : 0;
        int cnt = end - base;
        if (cnt > 32) cnt = 32;
#pragma unroll 4
        for (int k = 0; k < cnt; k++) {
            int s = __shfl_sync(0xffffffffu, sv, k);
            float2 a = *(const float2*)&g_xl[(size_t)s * DD + j];
            float m0 = a.x + xr2.x, m1 = a.y + xr2.y;
            m0 = (m0 > 0.f) ? m0 : 0.2f * m0;
            m1 = (m1 > 0.f) ? m1 : 0.2f * m1;
            float part = m0 * at2.x + m1 * at2.y;
            part += __shfl_xor_sync(0xffffffffu, part, 1);
            part += __shfl_xor_sync(0xffffffffu, part, 2);
            part += __shfl_xor_sync(0xffffffffu, part, 4);
            float p = __expf(part);
            accx = fmaf(p, a.x, accx);
            accy = fmaf(p, a.y, accy);
            den += p;
        }
    }

    // normalize + bias + residual
    float inv = 1.f / den;
    float2 xv = *(const float2*)&xres[(size_t)d * DD + j];
    float2 bi = *(const float2*)(bias + j);
    float v0 = accx * inv + bi.x + xv.x;
    float v1 = accy * inv + bi.y + xv.y;

    // LayerNorm over 64 channels (full-warp reduce)
    float s = v0 + v1;
    float s2 = v0 * v0 + v1 * v1;
#pragma unroll
    for (int o = 16; o; o >>= 1) {
        s += __shfl_xor_sync(0xffffffffu, s, o);
        s2 += __shfl_xor_sync(0xffffffffu, s2, o);
    }
    float mu = s * (1.f / 64.f);
    float var = s2 * (1.f / 64.f) - mu * mu;
    float rstd = rsqrtf(var + 1e-5f);

    float2 ga = *(const float2*)(gamma + j);
    float2 be = *(const float2*)(beta + j);
    float y0 = (v0 - mu) * rstd * ga.x + be.x;
    float y1 = (v1 - mu) * rstd * ga.y + be.y;

    // exact GeLU
    y0 = 0.5f * y0 * (1.f + erff(y0 * 0.70710678118654752f));
    y1 = 0.5f * y1 * (1.f + erff(y1 * 0.70710678118654752f));

    *(float2*)&out[(size_t)d * DD + j] = make_float2(y0, y1);
}

// ---------------------------------------------------------------------------
extern "C" void kernel_launch(void* const* d_in, const int* in_sizes, int n_in,
                              void* d_out, int out_size) {
    const float* x = (const float*)d_in[0];
    const int* ei = (const int*)d_in[1];   // int32: [src(E), dst(E)]
    const float* Wl = (const float*)d_in[2];
    const float* Wr = (const float*)d_in[3];
    const float* att = (const float*)d_in[4];
    const float* bias = (const float*)d_in[5];
    const float* gamma = (const float*)d_in[6];
    const float* beta = (const float*)d_in[7];

    int n = in_sizes[0] / DD;
    int E = in_sizes[1] / 2;
    int Lnum = in_sizes[2] / (DD * DD);

    float *b0p = nullptr, *b1p = nullptr;
    cudaGetSymbolAddress((void**)&b0p, g_b0);
    cudaGetSymbolAddress((void**)&b1p, g_b1);

    // ---- build CSR (dst-sorted edges) ----
    int nbScan = (n + SCAN_TILE - 1) / SCAN_TILE;
    k_cntzero<<<(n + 255) / 256, 256>>>(n);
    k_hist<<<(E + 255) / 256, 256>>>(ei, E);
    k_scan1<<<nbScan, SCAN_BLK>>>(n);
    k_scan2<<<1, 1024>>>(nbScan);
    k_scan3<<<(n + 1 + 255) / 256, 256>>>(n, E);
    k_scatter<<<(E + 255) / 256, 256>>>(ei, E);

    // ---- layers ----
    const float* cur = x;
    for (int i = 0; i < Lnum; i++) {
        k_gemm<<<(n + 63) / 64, 256>>>(cur, Wl + (size_t)i * DD * DD,
                                       Wr + (size_t)i * DD * DD, n);

        float* outp;
        if (i == Lnum - 1) outp = (float*)d_out;
        else outp = (i & 1) ? b1p : b0p;

        k_agg<<<((size_t)n * 32 + 255) / 256, 256>>>(cur, att + (size_t)i * DD,
                                                     bias + (size_t)i * DD,
                                                     gamma + (size_t)i * DD,
                                                     beta + (size_t)i * DD,
                                                     outp, n);
        cur = outp;
    }
}

// round 4
// speedup vs baseline: 1.1623x; 1.0362x over previous
#include <cuda_runtime.h>
#include <cuda_fp16.h>
#include <math.h>

// GATv2 (L=3, H=4, C=16, D=64), N=100000, E=1280000 (+N self loops).
// R4 design:
//  - CSR by dst (hist+scan+scatter, once per launch)
//  - GEMM writes xl in fp16 (128B row = 1 L2 line/edge gather) and xr in fp32
//  - fused agg: HALF-WARP per node (2 nodes/warp), 4 ch/lane, unnormalized
//    softmax (max-shift cancels), lrelu folded as m*0.6att + |m|*0.4att,
//    register acc, then normalize + bias + residual + LN + exact GeLU.

#define NNODES 100000
#define NEDGES 1280000
#define DD 64
#define SCAN_BLK 512
#define SCAN_ELEM 8
#define SCAN_TILE (SCAN_BLK * SCAN_ELEM)  // 4096

__device__ __align__(128) __half g_xlh[NNODES * DD];
__device__ __align__(16) float g_xr[NNODES * DD];
__device__ __align__(16) float g_b0[NNODES * DD];
__device__ __align__(16) float g_b1[NNODES * DD];
__device__ int g_cnt[NNODES];
__device__ int g_tmp[NNODES];
__device__ int g_ofs[NNODES];
__device__ int g_rowptr[NNODES + 1];
__device__ int g_bsum[1024];
__device__ int g_ssrc[NEDGES];

// ------------------------- CSR build (once per launch) ----------------------
__global__ void k_cntzero(int n) {
    int i = blockIdx.x * blockDim.x + threadIdx.x;
    if (i < n) g_cnt[i] = 0;
}

__global__ void k_hist(const int* __restrict__ ei, int E) {
    int e = blockIdx.x * blockDim.x + threadIdx.x;
    if (e < E) atomicAdd(&g_cnt[ei[E + e]], 1);
}

__global__ __launch_bounds__(SCAN_BLK) void k_scan1(int n) {
    __shared__ int sh[SCAN_BLK];
    int blk = blockIdx.x;
    int base = blk * SCAN_TILE + threadIdx.x * SCAN_ELEM;
    int t = threadIdx.x;
    int v[SCAN_ELEM];
    int sum = 0;
#pragma unroll
    for (int i = 0; i < SCAN_ELEM; i++) {
        int idx = base + i;
        v[i] = (idx < n) ? g_cnt[idx] : 0;
        sum += v[i];
    }
    sh[t] = sum;
    __syncthreads();
    for (int o = 1; o < SCAN_BLK; o <<= 1) {
        int x = (t >= o) ? sh[t - o] : 0;
        __syncthreads();
        sh[t] += x;
        __syncthreads();
    }
    int run = (t > 0) ? sh[t - 1] : 0;
    if (t == SCAN_BLK - 1) g_bsum[blk] = sh[t];
#pragma unroll
    for (int i = 0; i < SCAN_ELEM; i++) {
        int idx = base + i;
        if (idx < n) g_tmp[idx] = run;
        run += v[i];
    }
}

__global__ __launch_bounds__(1024) void k_scan2(int nb) {
    __shared__ int sh[1024];
    int t = threadIdx.x;
    sh[t] = (t < nb) ? g_bsum[t] : 0;
    __syncthreads();
    for (int o = 1; o < 1024; o <<= 1) {
        int x = (t >= o) ? sh[t - o] : 0;
        __syncthreads();
        sh[t] += x;
        __syncthreads();
    }
    g_bsum[t] = (t > 0) ? sh[t - 1] : 0;
}

__global__ void k_scan3(int n, int E) {
    int i = blockIdx.x * blockDim.x + threadIdx.x;
    if (i < n) {
        int r = g_tmp[i] + g_bsum[i / SCAN_TILE];
        g_rowptr[i] = r;
        g_ofs[i] = r;
    }
    if (i == n) g_rowptr[n] = E;
}

__global__ void k_scatter(const int* __restrict__ ei, int E) {
    int e = blockIdx.x * blockDim.x + threadIdx.x;
    if (e < E) {
        int d = ei[E + e];
        int pos = atomicAdd(&g_ofs[d], 1);
        g_ssrc[pos] = ei[e];
    }
}

// ---------------------------------------------------------------------------
// GEMM: xl = x @ Wl (-> fp16), xr = x @ Wr (-> fp32).  K = 64.
// ---------------------------------------------------------------------------
__global__ __launch_bounds__(256) void k_gemm(const float* __restrict__ x,
                                              const float* __restrict__ Wl,
                                              const float* __restrict__ Wr,
                                              int n) {
    __shared__ float sWl[64][64];
    __shared__ float sWr[64][64];
    __shared__ float sxT[64][64];

    int nodeBase = blockIdx.x * 64;

    for (int i = threadIdx.x; i < 64 * 64; i += 256) {
        sWl[i >> 6][i & 63] = Wl[i];
        sWr[i >> 6][i & 63] = Wr[i];
        int r = i >> 6, c = i & 63;
        int node = nodeBase + r;
        float v = (node < n) ? x[(size_t)node * DD + c] : 0.f;
        sxT[c][r] = v;
    }
    __syncthreads();

    int local = threadIdx.x >> 2;
    int cg = (threadIdx.x & 3) << 4;

    float accL[16], accR[16];
#pragma unroll
    for (int c = 0; c < 16; c++) { accL[c] = 0.f; accR[c] = 0.f; }

#pragma unroll 4
    for (int k = 0; k < 64; k++) {
        float xv = sxT[k][local];
        const float4* wl = (const float4*)&sWl[k][cg];
        const float4* wr = (const float4*)&sWr[k][cg];
#pragma unroll
        for (int q = 0; q < 4; q++) {
            float4 a = wl[q];
            float4 b = wr[q];
            accL[q * 4 + 0] = fmaf(xv, a.x, accL[q * 4 + 0]);
            accL[q * 4 + 1] = fmaf(xv, a.y, accL[q * 4 + 1]);
            accL[q * 4 + 2] = fmaf(xv, a.z, accL[q * 4 + 2]);
            accL[q * 4 + 3] = fmaf(xv, a.w, accL[q * 4 + 3]);
            accR[q * 4 + 0] = fmaf(xv, b.x, accR[q * 4 + 0]);
            accR[q * 4 + 1] = fmaf(xv, b.y, accR[q * 4 + 1]);
            accR[q * 4 + 2] = fmaf(xv, b.z, accR[q * 4 + 2]);
            accR[q * 4 + 3] = fmaf(xv, b.w, accR[q * 4 + 3]);
        }
    }

    int node = nodeBase + local;
    if (node < n) {
        // xl -> fp16
        __half2 hh[8];
#pragma unroll
        for (int q = 0; q < 8; q++)
            hh[q] = __floats2half2_rn(accL[2 * q], accL[2 * q + 1]);
        *(uint4*)&g_xlh[(size_t)node * DD + cg] = *(uint4*)&hh[0];
        *(uint4*)&g_xlh[(size_t)node * DD + cg + 8] = *(uint4*)&hh[4];

        float4* outr = (float4*)&g_xr[(size_t)node * DD + cg];
#pragma unroll
        for (int q = 0; q < 4; q++)
            outr[q] = make_float4(accR[q * 4 + 0], accR[q * 4 + 1], accR[q * 4 + 2], accR[q * 4 + 3]);
    }
}

// ---------------------------------------------------------------------------
// Fused aggregation: half-warp (16 lanes) per dst node, 4 channels per lane.
// Head = 16 ch = 4 lanes -> logit reduce is 2 shfl_xor. Edges gathered from
// CSR (sorted by dst) + implicit self loop.
// ---------------------------------------------------------------------------
__device__ __forceinline__ void edge_accum(int s, int j, unsigned mask16,
                                           const float4& xr4,
                                           const float4& a6, const float4& a4,
                                           float& acc0, float& acc1,
                                           float& acc2, float& acc3,
                                           float& den) {
    uint2 raw = *(const uint2*)&g_xlh[(size_t)s * DD + j];
    float2 a01 = __half22float2(*(__half2*)&raw.x);
    float2 a23 = __half22float2(*(__half2*)&raw.y);

    float m0 = a01.x + xr4.x;
    float m1 = a01.y + xr4.y;
    float m2 = a23.x + xr4.z;
    float m3 = a23.y + xr4.w;

    // lrelu(m)*att = m*(0.6att) + |m|*(0.4att)
    float part = m0 * a6.x;
    part = fmaf(fabsf(m0), a4.x, part);
    part = fmaf(m1, a6.y, part);
    part = fmaf(fabsf(m1), a4.y, part);
    part = fmaf(m2, a6.z, part);
    part = fmaf(fabsf(m2), a4.z, part);
    part = fmaf(m3, a6.w, part);
    part = fmaf(fabsf(m3), a4.w, part);

    part += __shfl_xor_sync(mask16, part, 1, 16);
    part += __shfl_xor_sync(mask16, part, 2, 16);

    float p = __expf(part);
    acc0 = fmaf(p, a01.x, acc0);
    acc1 = fmaf(p, a01.y, acc1);
    acc2 = fmaf(p, a23.x, acc2);
    acc3 = fmaf(p, a23.y, acc3);
    den += p;
}

__global__ __launch_bounds__(256) void k_agg(const float* __restrict__ xres,
                                             const float* __restrict__ att,
                                             const float* __restrict__ bias,
                                             const float* __restrict__ gamma,
                                             const float* __restrict__ beta,
                                             float* __restrict__ out, int n) {
    int warp = (blockIdx.x * blockDim.x + threadIdx.x) >> 5;
    int lane = threadIdx.x & 31;
    int hf = lane >> 4;
    int l16 = lane & 15;
    int d = warp * 2 + hf;
    if (d >= n) return;
    unsigned mask16 = hf ? 0xFFFF0000u : 0x0000FFFFu;
    int j = l16 * 4;

    float4 xr4 = *(const float4*)&g_xr[(size_t)d * DD + j];
    float4 at4 = *(const float4*)(att + j);
    float4 a6 = make_float4(0.6f * at4.x, 0.6f * at4.y, 0.6f * at4.z, 0.6f * at4.w);
    float4 a4 = make_float4(0.4f * at4.x, 0.4f * at4.y, 0.4f * at4.z, 0.4f * at4.w);

    float acc0 = 0.f, acc1 = 0.f, acc2 = 0.f, acc3 = 0.f, den = 0.f;

    // self loop
    edge_accum(d, j, mask16, xr4, a6, a4, acc0, acc1, acc2, acc3, den);

    int begin = g_rowptr[d];
    int end = g_rowptr[d + 1];

    for (int base = begin; base < end; base += 16) {
        int idx = base + l16;
        int sv = (idx < end) ? g_ssrc[idx] : 0;
        int cnt = end - base;
        if (cnt > 16) cnt = 16;
#pragma unroll 4
        for (int k = 0; k < cnt; k++) {
            int s = __shfl_sync(mask16, sv, k, 16);
            edge_accum(s, j, mask16, xr4, a6, a4, acc0, acc1, acc2, acc3, den);
        }
    }

    // normalize + bias + residual
    float inv = 1.f / den;
    float4 xv = *(const float4*)&xres[(size_t)d * DD + j];
    float4 bi = *(const float4*)(bias + j);
    float v0 = acc0 * inv + bi.x + xv.x;
    float v1 = acc1 * inv + bi.y + xv.y;
    float v2 = acc2 * inv + bi.z + xv.z;
    float v3 = acc3 * inv + bi.w + xv.w;

    // LayerNorm over 64 ch spread across 16 lanes
    float s = v0 + v1 + v2 + v3;
    float s2 = v0 * v0 + v1 * v1 + v2 * v2 + v3 * v3;
#pragma unroll
    for (int o = 8; o; o >>= 1) {
        s += __shfl_xor_sync(mask16, s, o, 16);
        s2 += __shfl_xor_sync(mask16, s2, o, 16);
    }
    float mu = s * (1.f / 64.f);
    float var = s2 * (1.f / 64.f) - mu * mu;
    float rstd = rsqrtf(var + 1e-5f);

    float4 ga = *(const float4*)(gamma + j);
    float4 be = *(const float4*)(beta + j);
    float y0 = (v0 - mu) * rstd * ga.x + be.x;
    float y1 = (v1 - mu) * rstd * ga.y + be.y;
    float y2 = (v2 - mu) * rstd * ga.z + be.z;
    float y3 = (v3 - mu) * rstd * ga.w + be.w;

    const float ks = 0.70710678118654752f;
    y0 = 0.5f * y0 * (1.f + erff(y0 * ks));
    y1 = 0.5f * y1 * (1.f + erff(y1 * ks));
    y2 = 0.5f * y2 * (1.f + erff(y2 * ks));
    y3 = 0.5f * y3 * (1.f + erff(y3 * ks));

    *(float4*)&out[(size_t)d * DD + j] = make_float4(y0, y1, y2, y3);
}

// ---------------------------------------------------------------------------
extern "C" void kernel_launch(void* const* d_in, const int* in_sizes, int n_in,
                              void* d_out, int out_size) {
    const float* x = (const float*)d_in[0];
    const int* ei = (const int*)d_in[1];   // int32: [src(E), dst(E)]
    const float* Wl = (const float*)d_in[2];
    const float* Wr = (const float*)d_in[3];
    const float* att = (const float*)d_in[4];
    const float* bias = (const float*)d_in[5];
    const float* gamma = (const float*)d_in[6];
    const float* beta = (const float*)d_in[7];

    int n = in_sizes[0] / DD;
    int E = in_sizes[1] / 2;
    int Lnum = in_sizes[2] / (DD * DD);

    float *b0p = nullptr, *b1p = nullptr;
    cudaGetSymbolAddress((void**)&b0p, g_b0);
    cudaGetSymbolAddress((void**)&b1p, g_b1);

    // ---- build CSR (dst-sorted edges) ----
    int nbScan = (n + SCAN_TILE - 1) / SCAN_TILE;
    k_cntzero<<<(n + 255) / 256, 256>>>(n);
    k_hist<<<(E + 255) / 256, 256>>>(ei, E);
    k_scan1<<<nbScan, SCAN_BLK>>>(n);
    k_scan2<<<1, 1024>>>(nbScan);
    k_scan3<<<(n + 1 + 255) / 256, 256>>>(n, E);
    k_scatter<<<(E + 255) / 256, 256>>>(ei, E);

    // ---- layers ----
    const float* cur = x;
    int aggBlocks = (n + 15) / 16;  // 16 nodes per 256-thread block
    for (int i = 0; i < Lnum; i++) {
        k_gemm<<<(n + 63) / 64, 256>>>(cur, Wl + (size_t)i * DD * DD,
                                       Wr + (size_t)i * DD * DD, n);

        float* outp;
        if (i == Lnum - 1) outp = (float*)d_out;
        else outp = (i & 1) ? b1p : b0p;

        k_agg<<<aggBlocks, 256>>>(cur, att + (size_t)i * DD,
                                  bias + (size_t)i * DD,
                                  gamma + (size_t)i * DD,
                                  beta + (size_t)i * DD,
                                  outp, n);
        cur = outp;
    }
}